// round 16
// baseline (speedup 1.0000x reference)
#include <cuda_runtime.h>
#include <cstdint>

#define DD 128
#define NMAX 50000
#define EMAX 800000
#define LAYERS 3
#define EPSV 1e-5f
#define PADK 136   // stride mod 32 = 8 -> bank = 8*lr + lq + c : conflict-free frags

// dynamic smem: W full hi+lo [128][PADK]x2 + A dbuf hi/lo [2][32][PADK]x2 + scale/shift
#define SMEM_GEMM ((2 * 128 * PADK + 4 * 32 * PADK) * 4 + 2 * DD * 4)

// ---- scratch (no allocs allowed) ----
__device__ float g_m[NMAX * DD];     // m = h @ W
__device__ float g_agg[NMAX * DD];   // aggregated messages (pre-BN)
__device__ float g_dinv[NMAX];       // rsqrt(deg)
__device__ int   g_cnt[NMAX];        // in-edge count per dst (no self-loop)
__device__ int   g_off[NMAX];        // per-node segment start (unordered alloc)
__device__ int   g_cur[NMAX];        // scatter cursors
__device__ int   g_total;            // segment allocator
__device__ int   g_es[EMAX];         // dst-grouped src ids
__device__ float g_ew[EMAX];         // dst-grouped edge weights dinv[s]*dinv[t]
__device__ uint32_t g_whi[LAYERS * DD * DD];  // W split hi (tf32 bits)
__device__ uint32_t g_wlo[LAYERS * DD * DD];  // W split lo (tf32 bits)
__device__ float g_sumL[LAYERS * DD];         // per-layer BN sums
__device__ float g_sumsqL[LAYERS * DD];

// ---------------- tf32 helpers ----------------
__device__ __forceinline__ void split_tf32(float v, uint32_t& hi, uint32_t& lo) {
    uint32_t h;
    asm("cvt.rna.tf32.f32 %0, %1;" : "=r"(h) : "f"(v));
    float l = v - __uint_as_float(h);
    uint32_t lw;
    asm("cvt.rna.tf32.f32 %0, %1;" : "=r"(lw) : "f"(l));
    hi = h; lo = lw;
}

__device__ __forceinline__ void mma_tf32(float* c, uint32_t a0, uint32_t a1,
                                         uint32_t a2, uint32_t a3,
                                         uint32_t b0, uint32_t b1) {
    asm volatile(
        "mma.sync.aligned.m16n8k8.row.col.f32.tf32.tf32.f32 "
        "{%0,%1,%2,%3}, {%4,%5,%6,%7}, {%8,%9}, {%0,%1,%2,%3};"
        : "+f"(c[0]), "+f"(c[1]), "+f"(c[2]), "+f"(c[3])
        : "r"(a0), "r"(a1), "r"(a2), "r"(a3), "r"(b0), "r"(b1));
}

// ---------------- GEMM-chain setup: split W + zero stats ----------------
__global__ void split_w_kernel(const float* __restrict__ W) {
    int i = blockIdx.x * blockDim.x + threadIdx.x;
    if (i < LAYERS * DD * DD) {
        uint32_t h, l;
        split_tf32(W[i], h, l);
        g_whi[i] = h;
        g_wlo[i] = l;
    }
    if (i < LAYERS * DD) { g_sumL[i] = 0.f; g_sumsqL[i] = 0.f; }
}

// ---------------- CSR chain ----------------
__global__ void zero_cnt_kernel(int n) {
    int i = blockIdx.x * blockDim.x + threadIdx.x;
    if (i < n) g_cnt[i] = 0;
    if (i == 0) g_total = 0;
}

__global__ void hist_kernel(const int* __restrict__ dst, int E) {
    int e = blockIdx.x * blockDim.x + threadIdx.x;
    if (e < E) atomicAdd(&g_cnt[dst[e]], 1);
}

// dinv + unordered segment allocation, fused
__global__ void alloc_dinv_kernel(int n) {
    int i = blockIdx.x * blockDim.x + threadIdx.x;
    if (i >= n) return;
    int c = g_cnt[i];
    g_dinv[i] = rsqrtf((float)(c + 1));  // +1 self-loop
    int pos = (c > 0) ? atomicAdd(&g_total, c) : 0;
    g_off[i] = pos;
    g_cur[i] = pos;
}

__global__ void edge_sort_kernel(const int* __restrict__ src,
                                 const int* __restrict__ dst, int E) {
    int e = blockIdx.x * blockDim.x + threadIdx.x;
    if (e >= E) return;
    int s = src[e], t = dst[e];
    int pos = atomicAdd(&g_cur[t], 1);
    g_es[pos] = s;
    g_ew[pos] = g_dinv[s] * g_dinv[t];
}

// ---------------- GEMM (3xTF32, pipelined): m = act(h) @ W ----------------
// 128 rows x 128 cols per block, 256 threads (8 warps, 4x2 warp grid).
// W hi/lo resident in smem for full K. A double-buffered: prefetch next
// chunk's gmem loads before computing current; ONE barrier per chunk.
__global__ __launch_bounds__(256) void gemm_tc_kernel(
    const float* __restrict__ x, int fused, int l,
    const float* __restrict__ gamma, const float* __restrict__ beta,
    float inv_n, int n)
{
    extern __shared__ char dyn[];
    uint32_t* bshF = (uint32_t*)dyn;                 // [128][PADK]
    uint32_t* bslF = bshF + 128 * PADK;              // [128][PADK]
    uint32_t* aThi = bslF + 128 * PADK;              // [2][32][PADK]
    uint32_t* aTlo = aThi + 2 * 32 * PADK;           // [2][32][PADK]
    float* s_scale = (float*)(aTlo + 2 * 32 * PADK);
    float* s_shift = s_scale + DD;

    const float* __restrict__ in = fused ? g_agg : x;
    int tid = threadIdx.x;
    if (tid < DD) {
        if (fused) {
            int pl = l - 1;
            float mu = g_sumL[pl * DD + tid] * inv_n;
            float var = g_sumsqL[pl * DD + tid] * inv_n - mu * mu;
            float rstd = rsqrtf(var + EPSV);
            float sc = gamma[pl * DD + tid] * rstd;
            s_scale[tid] = sc;
            s_shift[tid] = beta[pl * DD + tid] - mu * sc;
        } else {
            s_scale[tid] = 1.0f;
            s_shift[tid] = 0.0f;
        }
    }
    __syncthreads();   // s_scale/s_shift ready for staging

    int lane = tid & 31;
    int warp = tid >> 5;
    int warp_m = warp >> 1;            // rows warp_m*32 .. +31
    int warp_n = warp & 1;             // cols warp_n*64 .. +63
    int row0 = blockIdx.x * 128;
    int loff = l * DD * DD;

    // Full W hi/lo -> smem (coalesced uint4; W is tiny and launch-constant)
    for (int q = tid; q < 4096; q += 256) {
        int r = q >> 5, cq = q & 31;
        size_t gidx = (size_t)loff + (size_t)r * DD + cq * 4;
        *(uint4*)&bshF[r * PADK + cq * 4] = *(const uint4*)(g_whi + gidx);
        *(uint4*)&bslF[r * PADK + cq * 4] = *(const uint4*)(g_wlo + gidx);
    }

    // Per-thread A staging geometry: 4 float4 from one row
    int arow = tid & 127;              // warp lanes -> consecutive rows (STS conflict-free)
    int kqb = tid >> 7;                // 0 or 1
    int gr = row0 + arow;

    // stage chunk 0 into buffer 0
    {
#pragma unroll
        for (int j = 0; j < 4; j++) {
            int kq = kqb + 2 * j;      // 0..7 across (kqb, j)
            float4 v = make_float4(0.f, 0.f, 0.f, 0.f);
            if (gr < n)
                v = *(const float4*)(in + (size_t)gr * DD + kq * 4);
            if (fused) {
                int k = kq * 4;
                v.x = fmaxf(0.f, v.x * s_scale[k + 0] + s_shift[k + 0]);
                v.y = fmaxf(0.f, v.y * s_scale[k + 1] + s_shift[k + 1]);
                v.z = fmaxf(0.f, v.z * s_scale[k + 2] + s_shift[k + 2]);
                v.w = fmaxf(0.f, v.w * s_scale[k + 3] + s_shift[k + 3]);
            }
            uint32_t h0, l0, h1, l1, h2, l2, h3, l3;
            split_tf32(v.x, h0, l0);
            split_tf32(v.y, h1, l1);
            split_tf32(v.z, h2, l2);
            split_tf32(v.w, h3, l3);
            aThi[(kq * 4 + 0) * PADK + arow] = h0;
            aThi[(kq * 4 + 1) * PADK + arow] = h1;
            aThi[(kq * 4 + 2) * PADK + arow] = h2;
            aThi[(kq * 4 + 3) * PADK + arow] = h3;
            aTlo[(kq * 4 + 0) * PADK + arow] = l0;
            aTlo[(kq * 4 + 1) * PADK + arow] = l1;
            aTlo[(kq * 4 + 2) * PADK + arow] = l2;
            aTlo[(kq * 4 + 3) * PADK + arow] = l3;
        }
    }
    __syncthreads();   // chunk0 + full W ready

    float acc[2][8][4];
#pragma unroll
    for (int mt = 0; mt < 2; mt++)
#pragma unroll
        for (int nt = 0; nt < 8; nt++)
#pragma unroll
            for (int i = 0; i < 4; i++) acc[mt][nt][i] = 0.0f;

    int lq = lane >> 2;   // 0..7
    int lr = lane & 3;    // 0..3

    for (int ci = 0; ci < 4; ci++) {
        int cur = ci & 1;
        uint32_t* ah_s = aThi + cur * 32 * PADK;
        uint32_t* al_s = aTlo + cur * 32 * PADK;

        // prefetch next chunk's A into registers (latency hidden by MMAs below)
        float4 pf[4];
        if (ci < 3) {
            int ktn = (ci + 1) * 32;
#pragma unroll
            for (int j = 0; j < 4; j++) {
                int kq = kqb + 2 * j;
                pf[j] = make_float4(0.f, 0.f, 0.f, 0.f);
                if (gr < n)
                    pf[j] = *(const float4*)(in + (size_t)gr * DD + ktn + kq * 4);
            }
        }

        int wbase = ci * 32;
#pragma unroll
        for (int ks = 0; ks < 4; ks++) {
            int kk = ks * 8;
            uint32_t ah[2][4], al[2][4];
#pragma unroll
            for (int mt = 0; mt < 2; mt++) {
                int rb = warp_m * 32 + mt * 16 + lq;
                ah[mt][0] = ah_s[(kk + lr) * PADK + rb];
                ah[mt][1] = ah_s[(kk + lr) * PADK + rb + 8];
                ah[mt][2] = ah_s[(kk + lr + 4) * PADK + rb];
                ah[mt][3] = ah_s[(kk + lr + 4) * PADK + rb + 8];
                al[mt][0] = al_s[(kk + lr) * PADK + rb];
                al[mt][1] = al_s[(kk + lr) * PADK + rb + 8];
                al[mt][2] = al_s[(kk + lr + 4) * PADK + rb];
                al[mt][3] = al_s[(kk + lr + 4) * PADK + rb + 8];
            }
#pragma unroll
            for (int nt = 0; nt < 8; nt++) {
                int cb = warp_n * 64 + nt * 8 + lq;
                uint32_t bh0 = bshF[(wbase + kk + lr) * PADK + cb];
                uint32_t bh1 = bshF[(wbase + kk + lr + 4) * PADK + cb];
                uint32_t bl0 = bslF[(wbase + kk + lr) * PADK + cb];
                uint32_t bl1 = bslF[(wbase + kk + lr + 4) * PADK + cb];
#pragma unroll
                for (int mt = 0; mt < 2; mt++) {
                    mma_tf32(acc[mt][nt], ah[mt][0], ah[mt][1], ah[mt][2], ah[mt][3], bh0, bh1);
                    mma_tf32(acc[mt][nt], al[mt][0], al[mt][1], al[mt][2], al[mt][3], bh0, bh1);
                    mma_tf32(acc[mt][nt], ah[mt][0], ah[mt][1], ah[mt][2], ah[mt][3], bl0, bl1);
                }
            }
        }

        // transform + split + store prefetched chunk into the other buffer
        if (ci < 3) {
            int nb = cur ^ 1;
            uint32_t* dh = aThi + nb * 32 * PADK;
            uint32_t* dl = aTlo + nb * 32 * PADK;
            int ktn = (ci + 1) * 32;
#pragma unroll
            for (int j = 0; j < 4; j++) {
                int kq = kqb + 2 * j;
                float4 v = pf[j];
                if (fused) {
                    int k = ktn + kq * 4;
                    v.x = fmaxf(0.f, v.x * s_scale[k + 0] + s_shift[k + 0]);
                    v.y = fmaxf(0.f, v.y * s_scale[k + 1] + s_shift[k + 1]);
                    v.z = fmaxf(0.f, v.z * s_scale[k + 2] + s_shift[k + 2]);
                    v.w = fmaxf(0.f, v.w * s_scale[k + 3] + s_shift[k + 3]);
                }
                uint32_t h0, l0, h1, l1, h2, l2, h3, l3;
                split_tf32(v.x, h0, l0);
                split_tf32(v.y, h1, l1);
                split_tf32(v.z, h2, l2);
                split_tf32(v.w, h3, l3);
                dh[(kq * 4 + 0) * PADK + arow] = h0;
                dh[(kq * 4 + 1) * PADK + arow] = h1;
                dh[(kq * 4 + 2) * PADK + arow] = h2;
                dh[(kq * 4 + 3) * PADK + arow] = h3;
                dl[(kq * 4 + 0) * PADK + arow] = l0;
                dl[(kq * 4 + 1) * PADK + arow] = l1;
                dl[(kq * 4 + 2) * PADK + arow] = l2;
                dl[(kq * 4 + 3) * PADK + arow] = l3;
            }
            __syncthreads();   // next buffer ready; current buffer free
        }
    }

    // epilogue
#pragma unroll
    for (int mt = 0; mt < 2; mt++) {
        int gr0 = row0 + warp_m * 32 + mt * 16 + lq;
#pragma unroll
        for (int nt = 0; nt < 8; nt++) {
            int gc = warp_n * 64 + nt * 8 + lr * 2;
            if (gr0 < n)
                *(float2*)(g_m + (size_t)gr0 * DD + gc) =
                    make_float2(acc[mt][nt][0], acc[mt][nt][1]);
            if (gr0 + 8 < n)
                *(float2*)(g_m + (size_t)(gr0 + 8) * DD + gc) =
                    make_float2(acc[mt][nt][2], acc[mt][nt][3]);
        }
    }
}

// ---------------- gather + fused BN stats (proven; per-layer stat buffers) ----
__global__ __launch_bounds__(256) void gather_stats_kernel(int l, int n) {
    __shared__ float s_sum[8][DD];
    __shared__ float s_sq[8][DD];

    int tid = threadIdx.x;
    int lane = tid & 31;
    int warp = tid >> 5;
    int gwarp = blockIdx.x * 8 + warp;
    int nwarps = gridDim.x * 8;
    const float4* __restrict__ m4 = (const float4*)g_m;

    float4 lsum = make_float4(0.f, 0.f, 0.f, 0.f);
    float4 lsq  = make_float4(0.f, 0.f, 0.f, 0.f);

    for (int node = gwarp; node < n; node += nwarps) {
        float di = g_dinv[node];
        float w0 = di * di;
        float4 acc = m4[(size_t)node * 32 + lane];
        acc.x *= w0; acc.y *= w0; acc.z *= w0; acc.w *= w0;

        int beg = g_off[node];
        int cnt = g_cnt[node];
        for (int i = 0; i < cnt; i++) {
            int s = g_es[beg + i];
            float w = g_ew[beg + i];
            float4 v = m4[(size_t)s * 32 + lane];
            acc.x += w * v.x;
            acc.y += w * v.y;
            acc.z += w * v.z;
            acc.w += w * v.w;
        }
        ((float4*)g_agg)[(size_t)node * 32 + lane] = acc;

        lsum.x += acc.x; lsum.y += acc.y; lsum.z += acc.z; lsum.w += acc.w;
        lsq.x += acc.x * acc.x; lsq.y += acc.y * acc.y;
        lsq.z += acc.z * acc.z; lsq.w += acc.w * acc.w;
    }

    *(float4*)&s_sum[warp][lane * 4] = lsum;
    *(float4*)&s_sq[warp][lane * 4]  = lsq;
    __syncthreads();

    if (tid < DD) {
        float a = 0.f, b = 0.f;
#pragma unroll
        for (int w = 0; w < 8; w++) {
            a += s_sum[w][tid];
            b += s_sq[w][tid];
        }
        atomicAdd(&g_sumL[l * DD + tid], a);
        atomicAdd(&g_sumsqL[l * DD + tid], b);
    }
}

// ---------------- final normalize + relu -> out (computes own scale/shift) ----
__global__ void norm_relu_kernel(float* __restrict__ out,
                                 const float* __restrict__ gamma,
                                 const float* __restrict__ beta,
                                 float inv_n, int n) {
    __shared__ float s_scale[DD], s_shift[DD];
    int tid = threadIdx.x;
    if (tid < DD) {
        int pl = LAYERS - 1;
        float mu = g_sumL[pl * DD + tid] * inv_n;
        float var = g_sumsqL[pl * DD + tid] * inv_n - mu * mu;
        float rstd = rsqrtf(var + EPSV);
        float sc = gamma[pl * DD + tid] * rstd;
        s_scale[tid] = sc;
        s_shift[tid] = beta[pl * DD + tid] - mu * sc;
    }
    __syncthreads();

    int total = n * (DD / 4);
    for (int idx = blockIdx.x * blockDim.x + tid; idx < total;
         idx += gridDim.x * blockDim.x) {
        int c4 = (idx & 31) * 4;
        float4 v = ((const float4*)g_agg)[idx];
        float4 r;
        r.x = fmaxf(0.0f, v.x * s_scale[c4 + 0] + s_shift[c4 + 0]);
        r.y = fmaxf(0.0f, v.y * s_scale[c4 + 1] + s_shift[c4 + 1]);
        r.z = fmaxf(0.0f, v.z * s_scale[c4 + 2] + s_shift[c4 + 2]);
        r.w = fmaxf(0.0f, v.w * s_scale[c4 + 3] + s_shift[c4 + 3]);
        ((float4*)out)[idx] = r;
    }
}

// ---------------- launcher ----------------
extern "C" void kernel_launch(void* const* d_in, const int* in_sizes, int n_in,
                              void* d_out, int out_size) {
    const float* x     = (const float*)d_in[0];
    const int*   ei    = (const int*)d_in[1];
    const float* W     = (const float*)d_in[2];
    // d_in[3] = b : mathematically absorbed by batchnorm, unused
    const float* gamma = (const float*)d_in[4];
    const float* beta  = (const float*)d_in[5];
    float* out = (float*)d_out;

    int n = in_sizes[0] / DD;
    int E = in_sizes[1] / 2;
    const int* src = ei;
    const int* dst = ei + E;
    float inv_n = 1.0f / (float)n;

    cudaFuncSetAttribute(gemm_tc_kernel,
                         cudaFuncAttributeMaxDynamicSharedMemorySize, SMEM_GEMM);

    // fork: CSR chain on side stream, W-split + GEMM0 on launch stream
    cudaStream_t s2;
    cudaEvent_t ev_fork, ev_join;
    cudaStreamCreateWithFlags(&s2, cudaStreamNonBlocking);
    cudaEventCreateWithFlags(&ev_fork, cudaEventDisableTiming);
    cudaEventCreateWithFlags(&ev_join, cudaEventDisableTiming);

    cudaEventRecord(ev_fork, 0);
    cudaStreamWaitEvent(s2, ev_fork, 0);

    // CSR chain (side stream)
    zero_cnt_kernel<<<(n + 255) / 256, 256, 0, s2>>>(n);
    hist_kernel<<<(E + 255) / 256, 256, 0, s2>>>(dst, E);
    alloc_dinv_kernel<<<(n + 255) / 256, 256, 0, s2>>>(n);
    edge_sort_kernel<<<(E + 255) / 256, 256, 0, s2>>>(src, dst, E);
    cudaEventRecord(ev_join, s2);

    // GEMM chain (launch stream)
    split_w_kernel<<<(LAYERS * DD * DD + 255) / 256, 256>>>(W);
    gemm_tc_kernel<<<(n + 127) / 128, 256, SMEM_GEMM>>>(
        x, 0, 0, gamma, beta, inv_n, n);

    // join before first gather
    cudaStreamWaitEvent(0, ev_join, 0);

    gather_stats_kernel<<<512, 256>>>(0, n);
    for (int l = 1; l < LAYERS; l++) {
        gemm_tc_kernel<<<(n + 127) / 128, 256, SMEM_GEMM>>>(
            x, 1, l, gamma, beta, inv_n, n);
        gather_stats_kernel<<<512, 256>>>(l, n);
    }
    norm_relu_kernel<<<512, 256>>>(out, gamma, beta, inv_n, n);
}

// round 17
// speedup vs baseline: 1.1724x; 1.1724x over previous
#include <cuda_runtime.h>
#include <cstdint>

#define DD 128
#define NMAX 50000
#define EMAX 800000
#define LAYERS 3
#define EPSV 1e-5f
#define PADK 136   // stride mod 32 = 8 -> bank = 8*lr + lq + c : conflict-free frags

// dynamic smem: aT(32*PADK f32) + bsh(32*PADK u32) + bsl + scale + shift
#define SMEM_GEMM (32 * PADK * 4 * 3 + 2 * DD * 4)

// ---- scratch (no allocs allowed) ----
__device__ float g_m[NMAX * DD];     // m = h @ W
__device__ float g_agg[NMAX * DD];   // aggregated messages (pre-BN)
__device__ float g_dinv[NMAX];       // rsqrt(deg)
__device__ int   g_cnt[NMAX];        // in-edge count per dst (no self-loop)
__device__ int   g_off[NMAX];        // per-node segment start (unordered alloc)
__device__ int   g_cur[NMAX];        // scatter cursors
__device__ int   g_total;            // segment allocator
__device__ int   g_es[EMAX];         // dst-grouped src ids
__device__ float g_ew[EMAX];         // dst-grouped edge weights dinv[s]*dinv[t]
__device__ uint32_t g_whi[LAYERS * DD * DD];  // W split hi (tf32 bits)
__device__ uint32_t g_wlo[LAYERS * DD * DD];  // W split lo (tf32 bits)
__device__ float g_sumL[LAYERS * DD];         // per-layer BN sums
__device__ float g_sumsqL[LAYERS * DD];

// ---------------- tf32 helpers ----------------
__device__ __forceinline__ void split_tf32(float v, uint32_t& hi, uint32_t& lo) {
    uint32_t h;
    asm("cvt.rna.tf32.f32 %0, %1;" : "=r"(h) : "f"(v));
    float l = v - __uint_as_float(h);
    uint32_t lw;
    asm("cvt.rna.tf32.f32 %0, %1;" : "=r"(lw) : "f"(l));
    hi = h; lo = lw;
}

__device__ __forceinline__ void mma_tf32(float* c, uint32_t a0, uint32_t a1,
                                         uint32_t a2, uint32_t a3,
                                         uint32_t b0, uint32_t b1) {
    asm volatile(
        "mma.sync.aligned.m16n8k8.row.col.f32.tf32.tf32.f32 "
        "{%0,%1,%2,%3}, {%4,%5,%6,%7}, {%8,%9}, {%0,%1,%2,%3};"
        : "+f"(c[0]), "+f"(c[1]), "+f"(c[2]), "+f"(c[3])
        : "r"(a0), "r"(a1), "r"(a2), "r"(a3), "r"(b0), "r"(b1));
}

// ---------------- GEMM-chain setup: split W + zero stats ----------------
__global__ void split_w_kernel(const float* __restrict__ W) {
    int i = blockIdx.x * blockDim.x + threadIdx.x;
    if (i < LAYERS * DD * DD) {
        uint32_t h, l;
        split_tf32(W[i], h, l);
        g_whi[i] = h;
        g_wlo[i] = l;
    }
    if (i < LAYERS * DD) { g_sumL[i] = 0.f; g_sumsqL[i] = 0.f; }
}

// ---------------- CSR chain ----------------
__global__ void zero_cnt_kernel(int n) {
    int i = blockIdx.x * blockDim.x + threadIdx.x;
    if (i < n) g_cnt[i] = 0;
    if (i == 0) g_total = 0;
}

__global__ void hist_kernel(const int* __restrict__ dst, int E) {
    int e = blockIdx.x * blockDim.x + threadIdx.x;
    if (e < E) atomicAdd(&g_cnt[dst[e]], 1);
}

// dinv + unordered segment allocation, fused
__global__ void alloc_dinv_kernel(int n) {
    int i = blockIdx.x * blockDim.x + threadIdx.x;
    if (i >= n) return;
    int c = g_cnt[i];
    g_dinv[i] = rsqrtf((float)(c + 1));  // +1 self-loop
    int pos = (c > 0) ? atomicAdd(&g_total, c) : 0;
    g_off[i] = pos;
    g_cur[i] = pos;
}

__global__ void edge_sort_kernel(const int* __restrict__ src,
                                 const int* __restrict__ dst, int E) {
    int e = blockIdx.x * blockDim.x + threadIdx.x;
    if (e >= E) return;
    int s = src[e], t = dst[e];
    int pos = atomicAdd(&g_cur[t], 1);
    g_es[pos] = s;
    g_ew[pos] = g_dinv[s] * g_dinv[t];
}

// ---------------- GEMM (3xTF32, pre-split W, K-chunk 32): m = act(h) @ W ----
// R14-proven shape: 128x128 block, 256 threads, 4 blocks/SM.
__global__ __launch_bounds__(256) void gemm_tc_kernel(
    const float* __restrict__ x, int fused, int l,
    const float* __restrict__ gamma, const float* __restrict__ beta,
    float inv_n, int n)
{
    extern __shared__ char dyn[];
    float*    aT  = (float*)dyn;                          // [32][PADK]
    uint32_t* bsh = (uint32_t*)(dyn + 32 * PADK * 4);     // [32][PADK]
    uint32_t* bsl = bsh + 32 * PADK;                      // [32][PADK]
    float* s_scale = (float*)(bsl + 32 * PADK);
    float* s_shift = s_scale + DD;

    const float* __restrict__ in = fused ? g_agg : x;
    int tid = threadIdx.x;
    if (tid < DD) {
        if (fused) {
            int pl = l - 1;
            float mu = g_sumL[pl * DD + tid] * inv_n;
            float var = g_sumsqL[pl * DD + tid] * inv_n - mu * mu;
            float rstd = rsqrtf(var + EPSV);
            float sc = gamma[pl * DD + tid] * rstd;
            s_scale[tid] = sc;
            s_shift[tid] = beta[pl * DD + tid] - mu * sc;
        } else {
            s_scale[tid] = 1.0f;
            s_shift[tid] = 0.0f;
        }
    }
    __syncthreads();

    int lane = tid & 31;
    int warp = tid >> 5;
    int warp_m = warp >> 1;            // rows warp_m*32 .. +31
    int warp_n = warp & 1;             // cols warp_n*64 .. +63
    int row0 = blockIdx.x * 128;
    int loff = l * DD * DD;

    float acc[2][8][4];
#pragma unroll
    for (int mt = 0; mt < 2; mt++)
#pragma unroll
        for (int nt = 0; nt < 8; nt++)
#pragma unroll
            for (int i = 0; i < 4; i++) acc[mt][nt][i] = 0.0f;

    int lq = lane >> 2;   // 0..7
    int lr = lane & 3;    // 0..3

    for (int kt = 0; kt < DD; kt += 32) {
        // A chunk: 128 rows x 32 k, stored transposed. 1024 float4 gmem loads.
        for (int q = tid; q < 1024; q += 256) {
            int kq = q >> 7, row = q & 127;
            int gr = row0 + row;
            float4 v = make_float4(0.f, 0.f, 0.f, 0.f);
            if (gr < n)
                v = *(const float4*)(in + (size_t)gr * DD + kt + kq * 4);
            if (fused) {
                int k = kt + kq * 4;
                v.x = fmaxf(0.f, v.x * s_scale[k + 0] + s_shift[k + 0]);
                v.y = fmaxf(0.f, v.y * s_scale[k + 1] + s_shift[k + 1]);
                v.z = fmaxf(0.f, v.z * s_scale[k + 2] + s_shift[k + 2]);
                v.w = fmaxf(0.f, v.w * s_scale[k + 3] + s_shift[k + 3]);
            }
            aT[(kq * 4 + 0) * PADK + row] = v.x;
            aT[(kq * 4 + 1) * PADK + row] = v.y;
            aT[(kq * 4 + 2) * PADK + row] = v.z;
            aT[(kq * 4 + 3) * PADK + row] = v.w;
        }
        // W chunks hi+lo: 32 k x 128 cols each, coalesced uint4 loads.
        for (int q = tid; q < 1024; q += 256) {
            int r = q >> 5, cq = q & 31;
            size_t gidx = (size_t)loff + (size_t)(kt + r) * DD + cq * 4;
            *(uint4*)&bsh[r * PADK + cq * 4] = *(const uint4*)(g_whi + gidx);
            *(uint4*)&bsl[r * PADK + cq * 4] = *(const uint4*)(g_wlo + gidx);
        }
        __syncthreads();

#pragma unroll
        for (int ks = 0; ks < 4; ks++) {
            int kk = ks * 8;
            uint32_t ah[2][4], al[2][4];
#pragma unroll
            for (int mt = 0; mt < 2; mt++) {
                int rb = warp_m * 32 + mt * 16 + lq;
                float f0 = aT[(kk + lr) * PADK + rb];
                float f1 = aT[(kk + lr) * PADK + rb + 8];
                float f2 = aT[(kk + lr + 4) * PADK + rb];
                float f3 = aT[(kk + lr + 4) * PADK + rb + 8];
                split_tf32(f0, ah[mt][0], al[mt][0]);
                split_tf32(f1, ah[mt][1], al[mt][1]);
                split_tf32(f2, ah[mt][2], al[mt][2]);
                split_tf32(f3, ah[mt][3], al[mt][3]);
            }
#pragma unroll
            for (int nt = 0; nt < 8; nt++) {
                int cb = warp_n * 64 + nt * 8 + lq;
                uint32_t bh0 = bsh[(kk + lr) * PADK + cb];
                uint32_t bh1 = bsh[(kk + lr + 4) * PADK + cb];
                uint32_t bl0 = bsl[(kk + lr) * PADK + cb];
                uint32_t bl1 = bsl[(kk + lr + 4) * PADK + cb];
#pragma unroll
                for (int mt = 0; mt < 2; mt++) {
                    mma_tf32(acc[mt][nt], ah[mt][0], ah[mt][1], ah[mt][2], ah[mt][3], bh0, bh1);
                    mma_tf32(acc[mt][nt], al[mt][0], al[mt][1], al[mt][2], al[mt][3], bh0, bh1);
                    mma_tf32(acc[mt][nt], ah[mt][0], ah[mt][1], ah[mt][2], ah[mt][3], bl0, bl1);
                }
            }
        }
        __syncthreads();
    }

    // epilogue
#pragma unroll
    for (int mt = 0; mt < 2; mt++) {
        int gr0 = row0 + warp_m * 32 + mt * 16 + lq;
#pragma unroll
        for (int nt = 0; nt < 8; nt++) {
            int gc = warp_n * 64 + nt * 8 + lr * 2;
            if (gr0 < n)
                *(float2*)(g_m + (size_t)gr0 * DD + gc) =
                    make_float2(acc[mt][nt][0], acc[mt][nt][1]);
            if (gr0 + 8 < n)
                *(float2*)(g_m + (size_t)(gr0 + 8) * DD + gc) =
                    make_float2(acc[mt][nt][2], acc[mt][nt][3]);
        }
    }
}

// ---------------- gather + fused BN stats, 4-way batched edge loop ----------
__global__ __launch_bounds__(256) void gather_stats_kernel(int l, int n) {
    __shared__ float s_sum[8][DD];
    __shared__ float s_sq[8][DD];

    int tid = threadIdx.x;
    int lane = tid & 31;
    int warp = tid >> 5;
    int gwarp = blockIdx.x * 8 + warp;
    int nwarps = gridDim.x * 8;
    const float4* __restrict__ m4 = (const float4*)g_m;

    float4 lsum = make_float4(0.f, 0.f, 0.f, 0.f);
    float4 lsq  = make_float4(0.f, 0.f, 0.f, 0.f);

    for (int node = gwarp; node < n; node += nwarps) {
        float di = g_dinv[node];
        float w0s = di * di;
        float4 acc = m4[(size_t)node * 32 + lane];
        acc.x *= w0s; acc.y *= w0s; acc.z *= w0s; acc.w *= w0s;

        int beg = g_off[node];
        int cnt = g_cnt[node];
        int i = 0;
        // 4-way batches: 4 independent L2 row-loads in flight (MLP=4)
        for (; i + 4 <= cnt; i += 4) {
            int   s0 = g_es[beg + i + 0], s1 = g_es[beg + i + 1];
            int   s2 = g_es[beg + i + 2], s3 = g_es[beg + i + 3];
            float w0 = g_ew[beg + i + 0], w1 = g_ew[beg + i + 1];
            float w2 = g_ew[beg + i + 2], w3 = g_ew[beg + i + 3];
            float4 v0 = m4[(size_t)s0 * 32 + lane];
            float4 v1 = m4[(size_t)s1 * 32 + lane];
            float4 v2 = m4[(size_t)s2 * 32 + lane];
            float4 v3 = m4[(size_t)s3 * 32 + lane];
            acc.x += w0 * v0.x + w1 * v1.x + w2 * v2.x + w3 * v3.x;
            acc.y += w0 * v0.y + w1 * v1.y + w2 * v2.y + w3 * v3.y;
            acc.z += w0 * v0.z + w1 * v1.z + w2 * v2.z + w3 * v3.z;
            acc.w += w0 * v0.w + w1 * v1.w + w2 * v2.w + w3 * v3.w;
        }
        for (; i < cnt; i++) {
            int s = g_es[beg + i];
            float w = g_ew[beg + i];
            float4 v = m4[(size_t)s * 32 + lane];
            acc.x += w * v.x;
            acc.y += w * v.y;
            acc.z += w * v.z;
            acc.w += w * v.w;
        }
        ((float4*)g_agg)[(size_t)node * 32 + lane] = acc;

        lsum.x += acc.x; lsum.y += acc.y; lsum.z += acc.z; lsum.w += acc.w;
        lsq.x += acc.x * acc.x; lsq.y += acc.y * acc.y;
        lsq.z += acc.z * acc.z; lsq.w += acc.w * acc.w;
    }

    *(float4*)&s_sum[warp][lane * 4] = lsum;
    *(float4*)&s_sq[warp][lane * 4]  = lsq;
    __syncthreads();

    if (tid < DD) {
        float a = 0.f, b = 0.f;
#pragma unroll
        for (int w = 0; w < 8; w++) {
            a += s_sum[w][tid];
            b += s_sq[w][tid];
        }
        atomicAdd(&g_sumL[l * DD + tid], a);
        atomicAdd(&g_sumsqL[l * DD + tid], b);
    }
}

// ---------------- final normalize + relu -> out (computes own scale/shift) ----
__global__ void norm_relu_kernel(float* __restrict__ out,
                                 const float* __restrict__ gamma,
                                 const float* __restrict__ beta,
                                 float inv_n, int n) {
    __shared__ float s_scale[DD], s_shift[DD];
    int tid = threadIdx.x;
    if (tid < DD) {
        int pl = LAYERS - 1;
        float mu = g_sumL[pl * DD + tid] * inv_n;
        float var = g_sumsqL[pl * DD + tid] * inv_n - mu * mu;
        float rstd = rsqrtf(var + EPSV);
        float sc = gamma[pl * DD + tid] * rstd;
        s_scale[tid] = sc;
        s_shift[tid] = beta[pl * DD + tid] - mu * sc;
    }
    __syncthreads();

    int total = n * (DD / 4);
    for (int idx = blockIdx.x * blockDim.x + tid; idx < total;
         idx += gridDim.x * blockDim.x) {
        int c4 = (idx & 31) * 4;
        float4 v = ((const float4*)g_agg)[idx];
        float4 r;
        r.x = fmaxf(0.0f, v.x * s_scale[c4 + 0] + s_shift[c4 + 0]);
        r.y = fmaxf(0.0f, v.y * s_scale[c4 + 1] + s_shift[c4 + 1]);
        r.z = fmaxf(0.0f, v.z * s_scale[c4 + 2] + s_shift[c4 + 2]);
        r.w = fmaxf(0.0f, v.w * s_scale[c4 + 3] + s_shift[c4 + 3]);
        ((float4*)out)[idx] = r;
    }
}

// ---------------- launcher ----------------
extern "C" void kernel_launch(void* const* d_in, const int* in_sizes, int n_in,
                              void* d_out, int out_size) {
    const float* x     = (const float*)d_in[0];
    const int*   ei    = (const int*)d_in[1];
    const float* W     = (const float*)d_in[2];
    // d_in[3] = b : mathematically absorbed by batchnorm, unused
    const float* gamma = (const float*)d_in[4];
    const float* beta  = (const float*)d_in[5];
    float* out = (float*)d_out;

    int n = in_sizes[0] / DD;
    int E = in_sizes[1] / 2;
    const int* src = ei;
    const int* dst = ei + E;
    float inv_n = 1.0f / (float)n;

    cudaFuncSetAttribute(gemm_tc_kernel,
                         cudaFuncAttributeMaxDynamicSharedMemorySize, SMEM_GEMM);

    // fork: CSR chain on side stream, W-split + GEMM0 on launch stream
    cudaStream_t s2;
    cudaEvent_t ev_fork, ev_join;
    cudaStreamCreateWithFlags(&s2, cudaStreamNonBlocking);
    cudaEventCreateWithFlags(&ev_fork, cudaEventDisableTiming);
    cudaEventCreateWithFlags(&ev_join, cudaEventDisableTiming);

    cudaEventRecord(ev_fork, 0);
    cudaStreamWaitEvent(s2, ev_fork, 0);

    // CSR chain (side stream)
    zero_cnt_kernel<<<(n + 255) / 256, 256, 0, s2>>>(n);
    hist_kernel<<<(E + 255) / 256, 256, 0, s2>>>(dst, E);
    alloc_dinv_kernel<<<(n + 255) / 256, 256, 0, s2>>>(n);
    edge_sort_kernel<<<(E + 255) / 256, 256, 0, s2>>>(src, dst, E);
    cudaEventRecord(ev_join, s2);

    // GEMM chain (launch stream)
    split_w_kernel<<<(LAYERS * DD * DD + 255) / 256, 256>>>(W);
    gemm_tc_kernel<<<(n + 127) / 128, 256, SMEM_GEMM>>>(
        x, 0, 0, gamma, beta, inv_n, n);

    // join before first gather
    cudaStreamWaitEvent(0, ev_join, 0);

    gather_stats_kernel<<<512, 256>>>(0, n);
    for (int l = 1; l < LAYERS; l++) {
        gemm_tc_kernel<<<(n + 127) / 128, 256, SMEM_GEMM>>>(
            x, 1, l, gamma, beta, inv_n, n);
        gather_stats_kernel<<<512, 256>>>(l, n);
    }
    norm_relu_kernel<<<512, 256>>>(out, gamma, beta, inv_n, n);
}